// round 5
// baseline (speedup 1.0000x reference)
#include <cuda_runtime.h>
#include <cstdint>

// ============================================================================
// z = relu((A @ z) @ W_l), 2 layers.  A:[8192,8192] f32, z:[4,8192,64] f32.
// Rewrite: relu((A@Z)@W) == relu(A@(Z@W)).
//   prep  : Yt[c=b*64+g][n] = rna( SCOMP * sum_f z[b,n,f]*W[f,g] )   (tiny)
//   layer : D[m][c] = sum_k A[m][k]*Yt[c][k]  via mma.sync tf32 (sm_80+ path;
//           tcgen05 rejected by this harness's sm_100 ptxas target)
// 128 CTAs (64 M-tiles x 2 N-tiles), 256 thr, warp tile 32x64, K-chunk 32,
// 4-stage cp.async pipeline, stride-36 SMEM padding (conflict-free frags).
// ============================================================================

#define NN 8192
#define CC 256
#define FF 64
#define BB 4
#define MT 128
#define NT 128
#define KST 256                    // 8192 / 32 K-chunks
#define STRIDE 36                  // floats per SMEM row (conflict-free pad)
#define STAGE_FLOATS (256 * STRIDE)     // A(128 rows) + Y(128 rows)
#define SMEM_DYN (4 * STAGE_FLOATS * 4) // 147456 bytes

// tf32 truncation bias compensation (A operand raw fp32 -> HW truncates)
#define SCOMP 1.000352f

__device__ float g_y0[(size_t)CC * NN];
__device__ float g_y1[(size_t)CC * NN];
__device__ float g_h [(size_t)NN * CC];

// ---------------------------------------------------------------- helpers ---
static __device__ __forceinline__ uint32_t smem_u32(const void* p) {
    uint32_t a;
    asm("{ .reg .u64 t; cvta.to.shared.u64 t, %1; cvt.u32.u64 %0, t; }"
        : "=r"(a) : "l"(p));
    return a;
}
static __device__ __forceinline__ uint32_t f2tf32(float x) {
    uint32_t r;
    asm("cvt.rna.tf32.f32 %0, %1;" : "=r"(r) : "f"(x));
    return r;
}
static __device__ __forceinline__ void cpa16(uint32_t dst, const void* src) {
    asm volatile("cp.async.cg.shared.global [%0], [%1], 16;"
                 :: "r"(dst), "l"(src));
}
#define CP_COMMIT() asm volatile("cp.async.commit_group;" ::: "memory")
#define CP_WAIT(n)  asm volatile("cp.async.wait_group %0;" :: "n"(n) : "memory")

static __device__ __forceinline__ void mma8(float* d,
    uint32_t a0, uint32_t a1, uint32_t a2, uint32_t a3,
    uint32_t b0, uint32_t b1) {
    asm volatile(
        "mma.sync.aligned.m16n8k8.row.col.f32.tf32.tf32.f32 "
        "{%0,%1,%2,%3},{%4,%5,%6,%7},{%8,%9},{%0,%1,%2,%3};"
        : "+f"(d[0]), "+f"(d[1]), "+f"(d[2]), "+f"(d[3])
        : "r"(a0), "r"(a1), "r"(a2), "r"(a3), "r"(b0), "r"(b1));
}

// ============================================================= prep kernel ==
// Yt[(b*64+g)*NN + n] = rna( SCOMP * sum_f src(b,n,f) * W[f][g] )
__global__ void __launch_bounds__(256) prep_kernel(
    const float* __restrict__ src, long sB, long sN,
    const float* __restrict__ Wp, float* __restrict__ yt)
{
    __shared__ float zs[32][65];
    __shared__ float ws[FF * FF];
    int b  = blockIdx.y;
    int n0 = blockIdx.x * 32;
    int tid = threadIdx.x;

    for (int i = tid; i < FF * FF; i += 256) ws[i] = Wp[i];
    for (int i = tid; i < 32 * FF; i += 256) {
        int n = i >> 6, f = i & 63;
        zs[n][f] = src[(long)b * sB + (long)(n0 + n) * sN + f];
    }
    __syncthreads();

    int lane = tid & 31, w = tid >> 5;
    float zr[FF];
    #pragma unroll
    for (int f = 0; f < FF; f++) zr[f] = zs[lane][f];

    for (int gi = 0; gi < 8; gi++) {
        int g = w * 8 + gi;
        float acc = 0.f;
        #pragma unroll
        for (int f = 0; f < FF; f++) acc = fmaf(zr[f], ws[f * FF + g], acc);
        yt[(long)(b * FF + g) * NN + n0 + lane] =
            __uint_as_float(f2tf32(acc * SCOMP));
    }
}

// ============================================================ layer kernel ==
__global__ void __launch_bounds__(256, 1) layer_kernel(
    const float* __restrict__ A, const float* __restrict__ yt,
    float* __restrict__ dst, int final_layer)
{
    extern __shared__ float smem[];
    uint32_t sb = smem_u32(smem);
    int tid = threadIdx.x, wid = tid >> 5, lane = tid & 31;
    int g = lane >> 2, t = lane & 3;
    int m0 = (blockIdx.x >> 1) * MT;
    int n0 = (blockIdx.x & 1) * NT;

    // ---- per-thread load plan: 2048 granules / 256 threads = 8 each ----
    const float* gp[8];
    uint32_t so[8];                       // byte offset within stage
    #pragma unroll
    for (int j = 0; j < 8; j++) {
        int gr = tid + j * 256;
        if (gr < 1024) {                  // A tile: 128 rows x 32 floats
            int row = gr >> 3, k16 = gr & 7;
            gp[j] = A + (long)(m0 + row) * NN + k16 * 4;
            so[j] = (uint32_t)(row * STRIDE + k16 * 4) * 4u;
        } else {                          // Y tile: 128 rows x 32 floats
            int yy = gr - 1024, row = yy >> 3, k16 = yy & 7;
            gp[j] = yt + (long)(n0 + row) * NN + k16 * 4;
            so[j] = (uint32_t)((128 + row) * STRIDE + k16 * 4) * 4u;
        }
    }

    float acc[2][8][4];
    #pragma unroll
    for (int mi = 0; mi < 2; mi++)
        #pragma unroll
        for (int ni = 0; ni < 8; ni++)
            #pragma unroll
            for (int r = 0; r < 4; r++) acc[mi][ni][r] = 0.f;

    int wm = (wid >> 1) * 32;             // warp M offset: 0,32,64,96
    int wn = (wid & 1) * 64;              // warp N offset: 0,64

    // ---- prologue: fill stages 0..2 ----
    #pragma unroll
    for (int s = 0; s < 3; s++) {
        uint32_t sbase = sb + (uint32_t)s * (STAGE_FLOATS * 4);
        #pragma unroll
        for (int j = 0; j < 8; j++) { cpa16(sbase + so[j], gp[j]); gp[j] += 32; }
        CP_COMMIT();
    }

    // ---- main loop ----
    for (int i = 0; i < KST; i++) {
        CP_WAIT(2);                       // stage i landed
        __syncthreads();
        if (i + 3 < KST) {                // issue stage i+3 into slot (i+3)&3
            uint32_t sbase = sb + (uint32_t)((i + 3) & 3) * (STAGE_FLOATS * 4);
            #pragma unroll
            for (int j = 0; j < 8; j++) { cpa16(sbase + so[j], gp[j]); gp[j] += 32; }
        }
        CP_COMMIT();

        const float* As = smem + (i & 3) * STAGE_FLOATS;
        const float* Ys = As + 128 * STRIDE;
        #pragma unroll
        for (int ks = 0; ks < 4; ks++) {
            int k0 = ks * 8;
            uint32_t af[2][4];
            #pragma unroll
            for (int mi = 0; mi < 2; mi++) {
                const float* ap = As + (wm + mi * 16 + g) * STRIDE + k0 + t;
                af[mi][0] = __float_as_uint(ap[0]);
                af[mi][1] = __float_as_uint(ap[8 * STRIDE]);
                af[mi][2] = __float_as_uint(ap[4]);
                af[mi][3] = __float_as_uint(ap[8 * STRIDE + 4]);
            }
            uint32_t bf[8][2];
            #pragma unroll
            for (int ni = 0; ni < 8; ni++) {
                const float* bp = Ys + (wn + ni * 8 + g) * STRIDE + k0 + t;
                bf[ni][0] = __float_as_uint(bp[0]);
                bf[ni][1] = __float_as_uint(bp[4]);
            }
            #pragma unroll
            for (int mi = 0; mi < 2; mi++)
                #pragma unroll
                for (int ni = 0; ni < 8; ni++)
                    mma8(acc[mi][ni], af[mi][0], af[mi][1], af[mi][2], af[mi][3],
                         bf[ni][0], bf[ni][1]);
        }
        __syncthreads();                  // stage i free before slot reuse
    }

    // ---- epilogue: relu + store ----
    #pragma unroll
    for (int mi = 0; mi < 2; mi++) {
        #pragma unroll
        for (int ni = 0; ni < 8; ni++) {
            int r1 = m0 + wm + mi * 16 + g;
            int r2 = r1 + 8;
            int c  = n0 + wn + ni * 8 + 2 * t;
            float2 v01, v23;
            v01.x = fmaxf(acc[mi][ni][0], 0.f);
            v01.y = fmaxf(acc[mi][ni][1], 0.f);
            v23.x = fmaxf(acc[mi][ni][2], 0.f);
            v23.y = fmaxf(acc[mi][ni][3], 0.f);
            long o1, o2;
            if (final_layer) {
                o1 = (long)(c >> 6) * (long)(NN * FF) + (long)r1 * FF + (c & 63);
                o2 = (long)(c >> 6) * (long)(NN * FF) + (long)r2 * FF + (c & 63);
            } else {
                o1 = (long)r1 * CC + c;
                o2 = (long)r2 * CC + c;
            }
            *reinterpret_cast<float2*>(dst + o1) = v01;
            *reinterpret_cast<float2*>(dst + o2) = v23;
        }
    }
}

// ================================================================== launch ==
extern "C" void kernel_launch(void* const* d_in, const int* in_sizes, int n_in,
                              void* d_out, int out_size)
{
    const float *x = nullptr, *np = nullptr, *A = nullptr;
    for (int i = 0; i < n_in; i++) {
        if      (in_sizes[i] == BB * NN * FF) x  = (const float*)d_in[i];
        else if (in_sizes[i] == 2 * FF * FF)  np = (const float*)d_in[i];
        else if (in_sizes[i] == NN * NN)      A  = (const float*)d_in[i];
    }

    float *y0, *y1, *h;
    cudaGetSymbolAddress((void**)&y0, g_y0);
    cudaGetSymbolAddress((void**)&y1, g_y1);
    cudaGetSymbolAddress((void**)&h,  g_h);

    cudaFuncSetAttribute(layer_kernel,
                         cudaFuncAttributeMaxDynamicSharedMemorySize, SMEM_DYN);

    dim3 pg(NN / 32, BB);
    prep_kernel<<<pg, 256>>>(x, (long)NN * FF, (long)FF, np, y0);
    layer_kernel<<<(NN / MT) * 2, 256, SMEM_DYN>>>(A, y0, h, 0);
    prep_kernel<<<pg, 256>>>(h, (long)FF, (long)CC, np + FF * FF, y1);
    layer_kernel<<<(NN / MT) * 2, 256, SMEM_DYN>>>(A, y1, (float*)d_out, 1);
}

// round 6
// speedup vs baseline: 1.5228x; 1.5228x over previous
#include <cuda_runtime.h>
#include <cuda_fp16.h>
#include <cstdint>

// ============================================================================
// z = relu((A @ z) @ W_l), 2 layers.  A:[8192,8192] f32, z:[4,8192,64] f32.
// Rewrite: relu((A@Z)@W) == relu(A@(Z@W)).
//   convA : A fp32 -> fp16 (once, amortized over both layers)
//   prep  : Yt[c=b*64+g][n] = rn_f16( sum_f z[b,n,f]*W[f,g] )
//   layer : D[m][c] = sum_k A[m][k]*Yt[c][k] via mma.sync.m16n8k16.f16 (2x tf32
//           rate), K-chunk 64, 4-stage cp.async, ldmatrix frags, 1 bar/stage.
// ============================================================================

#define NN 8192
#define CC 256
#define FF 64
#define BB 4
#define MT 128
#define NT 128
#define KST 128                      // 8192 / 64 K-chunks
#define RSTRIDE 144                  // bytes per SMEM row (72 fp16, pad)
#define STAGE_BYTES (256 * RSTRIDE)  // A 128 rows + Y 128 rows
#define SMEM_DYN (4 * STAGE_BYTES)   // 147456

__device__ __half g_Ah[(size_t)NN * NN];    // 128 MB fp16 A
__device__ __half g_yh[(size_t)CC * NN];    // fp16 Y (reused both layers)
__device__ float  g_h [(size_t)NN * CC];    // fp32 layer-1 output

// ---------------------------------------------------------------- helpers ---
static __device__ __forceinline__ uint32_t smem_u32(const void* p) {
    uint32_t a;
    asm("{ .reg .u64 t; cvta.to.shared.u64 t, %1; cvt.u32.u64 %0, t; }"
        : "=r"(a) : "l"(p));
    return a;
}
static __device__ __forceinline__ void cpa16(uint32_t dst, const void* src) {
    asm volatile("cp.async.cg.shared.global [%0], [%1], 16;"
                 :: "r"(dst), "l"(src));
}
#define CP_COMMIT() asm volatile("cp.async.commit_group;" ::: "memory")
#define CP_WAIT(n)  asm volatile("cp.async.wait_group %0;" :: "n"(n) : "memory")

static __device__ __forceinline__ void ldsm4(uint32_t* r, uint32_t addr) {
    asm volatile("ldmatrix.sync.aligned.m8n8.x4.shared.b16 {%0,%1,%2,%3}, [%4];"
                 : "=r"(r[0]), "=r"(r[1]), "=r"(r[2]), "=r"(r[3]) : "r"(addr));
}
static __device__ __forceinline__ void mma16(float* d,
    uint32_t a0, uint32_t a1, uint32_t a2, uint32_t a3,
    uint32_t b0, uint32_t b1) {
    asm volatile(
        "mma.sync.aligned.m16n8k16.row.col.f32.f16.f16.f32 "
        "{%0,%1,%2,%3},{%4,%5,%6,%7},{%8,%9},{%0,%1,%2,%3};"
        : "+f"(d[0]), "+f"(d[1]), "+f"(d[2]), "+f"(d[3])
        : "r"(a0), "r"(a1), "r"(a2), "r"(a3), "r"(b0), "r"(b1));
}

// ============================================================ convA kernel ==
__global__ void __launch_bounds__(256) convA_kernel(
    const float* __restrict__ A, __half* __restrict__ Ah)
{
    long i = ((long)blockIdx.x * 256 + threadIdx.x) * 8;
    float4 v0 = *reinterpret_cast<const float4*>(A + i);
    float4 v1 = *reinterpret_cast<const float4*>(A + i + 4);
    __half2 h[4];
    h[0] = __floats2half2_rn(v0.x, v0.y);
    h[1] = __floats2half2_rn(v0.z, v0.w);
    h[2] = __floats2half2_rn(v1.x, v1.y);
    h[3] = __floats2half2_rn(v1.z, v1.w);
    *reinterpret_cast<uint4*>(Ah + i) = *reinterpret_cast<uint4*>(h);
}

// ============================================================= prep kernel ==
// Yt[(b*64+g)*NN + n] = rn_f16( sum_f src(b,n,f) * W[f][g] )
__global__ void __launch_bounds__(256) prep_kernel(
    const float* __restrict__ src, long sB, long sN,
    const float* __restrict__ Wp, __half* __restrict__ yt)
{
    __shared__ float zs[32][65];
    __shared__ float ws[FF * FF];
    int b  = blockIdx.y;
    int n0 = blockIdx.x * 32;
    int tid = threadIdx.x;

    for (int i = tid; i < FF * FF; i += 256) ws[i] = Wp[i];
    for (int i = tid; i < 32 * FF; i += 256) {
        int n = i >> 6, f = i & 63;
        zs[n][f] = src[(long)b * sB + (long)(n0 + n) * sN + f];
    }
    __syncthreads();

    int lane = tid & 31, w = tid >> 5;
    float zr[FF];
    #pragma unroll
    for (int f = 0; f < FF; f++) zr[f] = zs[lane][f];

    for (int gi = 0; gi < 8; gi++) {
        int g = w * 8 + gi;
        float acc = 0.f;
        #pragma unroll
        for (int f = 0; f < FF; f++) acc = fmaf(zr[f], ws[f * FF + g], acc);
        yt[(long)(b * FF + g) * NN + n0 + lane] = __float2half_rn(acc);
    }
}

// ============================================================ layer kernel ==
// 128 CTAs (64 M x 2 N), 256 thr. Warp grid 4Mx2N, warp tile 32x64.
__global__ void __launch_bounds__(256, 1) layer_kernel(
    const __half* __restrict__ Ah, const __half* __restrict__ yt,
    float* __restrict__ dst, int final_layer)
{
    extern __shared__ char smem[];
    uint32_t sb = smem_u32(smem);
    int tid = threadIdx.x, wid = tid >> 5, lane = tid & 31;
    int g = lane >> 2, t = lane & 3;
    int m0 = (blockIdx.x >> 1) * MT;
    int n0 = (blockIdx.x & 1) * NT;
    int wm = (wid >> 1) * 32;            // warp M offset: 0,32,64,96
    int wn = (wid & 1) * 64;             // warp N offset: 0,64

    // ---- cp.async plan: 2048 granules (16B) / 256 thr = 8 per thread ----
    const __half* gp[8];
    uint32_t so[8];
    #pragma unroll
    for (int j = 0; j < 8; j++) {
        int gr = tid + j * 256;
        if (gr < 1024) {                 // A: 128 rows x 64 k fp16
            int row = gr >> 3, k8 = gr & 7;
            gp[j] = Ah + (long)(m0 + row) * NN + k8 * 8;
            so[j] = (uint32_t)(row * RSTRIDE + k8 * 16);
        } else {                         // Y: 128 c-rows x 64 k fp16
            int yy = gr - 1024, row = yy >> 3, k8 = yy & 7;
            gp[j] = yt + (long)(n0 + row) * NN + k8 * 8;
            so[j] = (uint32_t)((128 + row) * RSTRIDE + k8 * 16);
        }
    }

    // ---- ldmatrix per-lane base offsets (bytes within stage) ----
    int lr = lane & 15, lc = lane >> 4;  // 16x16 tile: row lr, k-half lc
    uint32_t aoff[2], boff[4];
    #pragma unroll
    for (int mi = 0; mi < 2; mi++)
        aoff[mi] = (uint32_t)((wm + mi * 16 + lr) * RSTRIDE + lc * 16);
    #pragma unroll
    for (int j = 0; j < 4; j++)
        boff[j] = (uint32_t)((128 + wn + j * 16 + lr) * RSTRIDE + lc * 16);

    float acc[2][8][4];
    #pragma unroll
    for (int mi = 0; mi < 2; mi++)
        #pragma unroll
        for (int ni = 0; ni < 8; ni++)
            #pragma unroll
            for (int r = 0; r < 4; r++) acc[mi][ni][r] = 0.f;

    // ---- prologue: stages 0..2 ----
    #pragma unroll
    for (int s = 0; s < 3; s++) {
        uint32_t sbase = sb + (uint32_t)s * STAGE_BYTES;
        #pragma unroll
        for (int j = 0; j < 8; j++) { cpa16(sbase + so[j], gp[j]); gp[j] += 64; }
        CP_COMMIT();
    }

    uint32_t af[2][2][4], bf[2][4][4];   // double-buffered fragments

    // ---- main loop: 128 x 64-K stages, ONE barrier per stage ----
    for (int i = 0; i < KST; i++) {
        CP_WAIT(2);                      // stage i landed
        __syncthreads();                 // also orders last iter's reads
        if (i + 3 < KST) {               // prefetch stage i+3
            uint32_t sbase = sb + (uint32_t)((i + 3) & 3) * STAGE_BYTES;
            #pragma unroll
            for (int j = 0; j < 8; j++) { cpa16(sbase + so[j], gp[j]); gp[j] += 64; }
        }
        CP_COMMIT();

        uint32_t stg = sb + (uint32_t)(i & 3) * STAGE_BYTES;
        // load kstep 0 fragments
        #pragma unroll
        for (int mi = 0; mi < 2; mi++) ldsm4(af[0][mi], stg + aoff[mi]);
        #pragma unroll
        for (int j = 0; j < 4; j++)    ldsm4(bf[0][j], stg + boff[j]);

        #pragma unroll
        for (int ks = 0; ks < 4; ks++) {
            int cur = ks & 1, nxt = cur ^ 1;
            if (ks < 3) {
                uint32_t ko = (uint32_t)((ks + 1) * 32);  // 16 k * 2B
                #pragma unroll
                for (int mi = 0; mi < 2; mi++) ldsm4(af[nxt][mi], stg + aoff[mi] + ko);
                #pragma unroll
                for (int j = 0; j < 4; j++)    ldsm4(bf[nxt][j], stg + boff[j] + ko);
            }
            #pragma unroll
            for (int mi = 0; mi < 2; mi++)
                #pragma unroll
                for (int j = 0; j < 4; j++) {
                    // j-th ldsm4 covers ni=2j (regs 0,2) and ni=2j+1 (regs 1,3)
                    mma16(acc[mi][2 * j],     af[cur][mi][0], af[cur][mi][1],
                          af[cur][mi][2], af[cur][mi][3],
                          bf[cur][j][0], bf[cur][j][2]);
                    mma16(acc[mi][2 * j + 1], af[cur][mi][0], af[cur][mi][1],
                          af[cur][mi][2], af[cur][mi][3],
                          bf[cur][j][1], bf[cur][j][3]);
                }
        }
    }

    // ---- epilogue: relu + store ----
    #pragma unroll
    for (int mi = 0; mi < 2; mi++) {
        #pragma unroll
        for (int ni = 0; ni < 8; ni++) {
            int r1 = m0 + wm + mi * 16 + g;
            int r2 = r1 + 8;
            int c  = n0 + wn + ni * 8 + 2 * t;
            float2 v01, v23;
            v01.x = fmaxf(acc[mi][ni][0], 0.f);
            v01.y = fmaxf(acc[mi][ni][1], 0.f);
            v23.x = fmaxf(acc[mi][ni][2], 0.f);
            v23.y = fmaxf(acc[mi][ni][3], 0.f);
            long o1, o2;
            if (final_layer) {
                o1 = (long)(c >> 6) * (long)(NN * FF) + (long)r1 * FF + (c & 63);
                o2 = (long)(c >> 6) * (long)(NN * FF) + (long)r2 * FF + (c & 63);
            } else {
                o1 = (long)r1 * CC + c;
                o2 = (long)r2 * CC + c;
            }
            *reinterpret_cast<float2*>(dst + o1) = v01;
            *reinterpret_cast<float2*>(dst + o2) = v23;
        }
    }
}

// ================================================================== launch ==
extern "C" void kernel_launch(void* const* d_in, const int* in_sizes, int n_in,
                              void* d_out, int out_size)
{
    const float *x = nullptr, *np = nullptr, *A = nullptr;
    for (int i = 0; i < n_in; i++) {
        if      (in_sizes[i] == BB * NN * FF) x  = (const float*)d_in[i];
        else if (in_sizes[i] == 2 * FF * FF)  np = (const float*)d_in[i];
        else if (in_sizes[i] == NN * NN)      A  = (const float*)d_in[i];
    }

    __half *Ah, *yh;
    float *h;
    cudaGetSymbolAddress((void**)&Ah, g_Ah);
    cudaGetSymbolAddress((void**)&yh, g_yh);
    cudaGetSymbolAddress((void**)&h,  g_h);

    cudaFuncSetAttribute(layer_kernel,
                         cudaFuncAttributeMaxDynamicSharedMemorySize, SMEM_DYN);

    convA_kernel<<<(int)(((long)NN * NN) / (256 * 8)), 256>>>(A, Ah);

    dim3 pg(NN / 32, BB);
    prep_kernel<<<pg, 256>>>(x, (long)NN * FF, (long)FF, np, yh);
    layer_kernel<<<(NN / MT) * 2, 256, SMEM_DYN>>>(Ah, yh, h, 0);
    prep_kernel<<<pg, 256>>>(h, (long)FF, (long)CC, np + FF * FF, yh);
    layer_kernel<<<(NN / MT) * 2, 256, SMEM_DYN>>>(Ah, yh, (float*)d_out, 1);
}